// round 1
// baseline (speedup 1.0000x reference)
#include <cuda_runtime.h>
#include <cuda_bf16.h>
#include <cstdint>

// Problem constants
#define BB 2
#define NN 4096
#define MM 4096
#define DD 512
#define HH 8
#define PP 64

// ---------------- scratch for projected Q/K/V ----------------
__device__ float g_Q[(size_t)BB * NN * DD];
__device__ float g_K[(size_t)BB * MM * DD];
__device__ float g_V[(size_t)BB * MM * DD];

// ---------------- projection GEMM: Y[R,512] = X[R,512] @ W[512,512] + b ----------------
#define GBM 64
#define GBN 64
#define GBK 16

__global__ __launch_bounds__(256) void gemm_bias_kernel(
    const float* __restrict__ X, const float* __restrict__ W,
    const float* __restrict__ bias, float* __restrict__ Y)
{
    __shared__ float Xs[GBK][GBM];   // transposed X tile
    __shared__ float Ws[GBK][GBN];

    const int bm = blockIdx.y * GBM;
    const int bn = blockIdx.x * GBN;
    const int tid = threadIdx.x;
    const int ty = tid >> 4;         // 0..15
    const int tx = tid & 15;         // 0..15

    float acc[4][4];
#pragma unroll
    for (int i = 0; i < 4; i++)
#pragma unroll
        for (int j = 0; j < 4; j++) acc[i][j] = 0.f;

    for (int k0 = 0; k0 < DD; k0 += GBK) {
        // load X tile [GBM x GBK]: 64 rows x 4 float4
        {
            int r = tid >> 2;       // 0..63
            int v = tid & 3;        // 0..3
            float4 x4 = *(const float4*)(X + (size_t)(bm + r) * DD + k0 + v * 4);
            Xs[v * 4 + 0][r] = x4.x;
            Xs[v * 4 + 1][r] = x4.y;
            Xs[v * 4 + 2][r] = x4.z;
            Xs[v * 4 + 3][r] = x4.w;
            // load W tile [GBK x GBN]: 16 rows x 16 float4
            int wr = tid >> 4;      // 0..15
            int wc = tid & 15;      // 0..15
            *(float4*)(&Ws[wr][wc * 4]) =
                *(const float4*)(W + (size_t)(k0 + wr) * DD + bn + wc * 4);
        }
        __syncthreads();

#pragma unroll
        for (int k = 0; k < GBK; k++) {
            float4 a4 = *(const float4*)(&Xs[k][ty * 4]);
            float4 b4 = *(const float4*)(&Ws[k][tx * 4]);
            float a[4] = {a4.x, a4.y, a4.z, a4.w};
            float b[4] = {b4.x, b4.y, b4.z, b4.w};
#pragma unroll
            for (int i = 0; i < 4; i++)
#pragma unroll
                for (int j = 0; j < 4; j++)
                    acc[i][j] += a[i] * b[j];
        }
        __syncthreads();
    }

    const float4 bv = *(const float4*)(bias + bn + tx * 4);
#pragma unroll
    for (int i = 0; i < 4; i++) {
        int row = bm + ty * 4 + i;
        float4 o;
        o.x = acc[i][0] + bv.x;
        o.y = acc[i][1] + bv.y;
        o.z = acc[i][2] + bv.z;
        o.w = acc[i][3] + bv.w;
        *(float4*)(Y + (size_t)row * DD + bn + tx * 4) = o;
    }
}

// ---------------- flash attention (fp32, online softmax) ----------------
// 1 thread = 1 query row. TILE_Q=128 queries/block, TILE_KV=32 keys/iter.
#define TQ 128
#define TK 32
#define PAD 68   // floats per smem row (64 data + 4 pad): conflict-free LDS.128 column access

// dynamic smem: qs[TQ][PAD] + ks[TK][PAD] + vs[TK][PAD]
#define FLASH_SMEM_FLOATS (TQ * PAD + 2 * TK * PAD)
#define FLASH_SMEM_BYTES  (FLASH_SMEM_FLOATS * 4)

__global__ __launch_bounds__(TQ) void flash_kernel(float* __restrict__ out)
{
    extern __shared__ float sm[];
    float* qs = sm;                       // [TQ][PAD]
    float* ks = qs + TQ * PAD;            // [TK][PAD]
    float* vs = ks + TK * PAD;            // [TK][PAD]

    const int n0 = blockIdx.x * TQ;
    const int h  = blockIdx.y;
    const int b  = blockIdx.z;
    const int tid = threadIdx.x;

    const float* Qb = g_Q + ((size_t)b * NN + n0) * DD + h * PP;
    const float* Kb = g_K + (size_t)b * MM * DD + h * PP;
    const float* Vb = g_V + (size_t)b * MM * DD + h * PP;

    // cooperative q-tile load: TQ rows x 16 float4
    for (int i = tid; i < TQ * 16; i += TQ) {
        int r = i >> 4, c = i & 15;
        *(float4*)(qs + r * PAD + c * 4) = *(const float4*)(Qb + (size_t)r * DD + c * 4);
    }

    float m = -1e30f, l = 0.f;
    float acc[PP];
#pragma unroll
    for (int p = 0; p < PP; p++) acc[p] = 0.f;

    __syncthreads();

    const float* qrow = qs + tid * PAD;

    for (int kt = 0; kt < MM; kt += TK) {
        // cooperative k/v tile load: TK rows x 16 float4 each
        for (int i = tid; i < TK * 16; i += TQ) {
            int r = i >> 4, c = i & 15;
            *(float4*)(ks + r * PAD + c * 4) = *(const float4*)(Kb + (size_t)(kt + r) * DD + c * 4);
            *(float4*)(vs + r * PAD + c * 4) = *(const float4*)(Vb + (size_t)(kt + r) * DD + c * 4);
        }
        __syncthreads();

        // scores for this thread's query row
        float s[TK];
        float tmax = -1e30f;
#pragma unroll
        for (int j = 0; j < TK; j++) {
            const float* krow = ks + j * PAD;
            float sx = 0.f, sy = 0.f, sz = 0.f, sw = 0.f;
#pragma unroll
            for (int c = 0; c < 16; c++) {
                float4 q4 = *(const float4*)(qrow + c * 4);
                float4 k4 = *(const float4*)(krow + c * 4);
                sx += q4.x * k4.x;
                sy += q4.y * k4.y;
                sz += q4.z * k4.z;
                sw += q4.w * k4.w;
            }
            float sj = ((sx + sy) + (sz + sw)) * 0.125f;  // 1/sqrt(64)
            s[j] = sj;
            tmax = fmaxf(tmax, sj);
        }

        if (tmax > m) {
            float corr = __expf(m - tmax);
            l *= corr;
#pragma unroll
            for (int p = 0; p < PP; p++) acc[p] *= corr;
            m = tmax;
        }

#pragma unroll
        for (int j = 0; j < TK; j++) {
            float pj = __expf(s[j] - m);
            l += pj;
            const float* vrow = vs + j * PAD;
#pragma unroll
            for (int c = 0; c < 16; c++) {
                float4 v4 = *(const float4*)(vrow + c * 4);
                acc[c * 4 + 0] += pj * v4.x;
                acc[c * 4 + 1] += pj * v4.y;
                acc[c * 4 + 2] += pj * v4.z;
                acc[c * 4 + 3] += pj * v4.w;
            }
        }
        __syncthreads();
    }

    const float inv = 1.f / l;
    float* ob = out + ((size_t)b * NN + n0 + tid) * DD + h * PP;
#pragma unroll
    for (int c = 0; c < 16; c++) {
        float4 o;
        o.x = acc[c * 4 + 0] * inv;
        o.y = acc[c * 4 + 1] * inv;
        o.z = acc[c * 4 + 2] * inv;
        o.w = acc[c * 4 + 3] * inv;
        *(float4*)(ob + c * 4) = o;
    }
}

// ---------------- launch ----------------
extern "C" void kernel_launch(void* const* d_in, const int* in_sizes, int n_in,
                              void* d_out, int out_size)
{
    const float* queries = (const float*)d_in[0];
    const float* keys    = (const float*)d_in[1];
    const float* values  = (const float*)d_in[2];
    const float* Wq      = (const float*)d_in[3];
    const float* bq      = (const float*)d_in[4];
    const float* Wk      = (const float*)d_in[5];
    const float* bk      = (const float*)d_in[6];
    const float* Wv      = (const float*)d_in[7];
    const float* bv      = (const float*)d_in[8];
    float* out = (float*)d_out;

    float *pQ, *pK, *pV;
    cudaGetSymbolAddress((void**)&pQ, g_Q);
    cudaGetSymbolAddress((void**)&pK, g_K);
    cudaGetSymbolAddress((void**)&pV, g_V);

    // projections: [8192, 512] @ [512, 512] + b
    dim3 ggrid(DD / GBN, (BB * NN) / GBM);
    gemm_bias_kernel<<<ggrid, 256>>>(queries, Wq, bq, pQ);
    gemm_bias_kernel<<<ggrid, 256>>>(keys,    Wk, bk, pK);
    gemm_bias_kernel<<<ggrid, 256>>>(values,  Wv, bv, pV);

    // flash attention
    cudaFuncSetAttribute(flash_kernel, cudaFuncAttributeMaxDynamicSharedMemorySize,
                         FLASH_SMEM_BYTES);
    dim3 fgrid(NN / TQ, HH, BB);
    flash_kernel<<<fgrid, TQ, FLASH_SMEM_BYTES>>>(out);
}

// round 5
// speedup vs baseline: 2.5664x; 2.5664x over previous
#include <cuda_runtime.h>
#include <cuda_bf16.h>
#include <cstdint>

// Problem constants
#define BB 2
#define NN 4096
#define MM 4096
#define DD 512
#define HH 8
#define PP 64

// ---------------- scratch for projected Q/K/V ----------------
__device__ float g_Q[(size_t)BB * NN * DD];
__device__ float g_K[(size_t)BB * MM * DD];
__device__ float g_V[(size_t)BB * MM * DD];

// ---------------- projection GEMM (fp32, unchanged: exact) ----------------
#define GBM 64
#define GBN 64
#define GBK 16

__global__ __launch_bounds__(256) void gemm_bias_kernel(
    const float* __restrict__ X, const float* __restrict__ W,
    const float* __restrict__ bias, float* __restrict__ Y)
{
    __shared__ float Xs[GBK][GBM];
    __shared__ float Ws[GBK][GBN];

    const int bm = blockIdx.y * GBM;
    const int bn = blockIdx.x * GBN;
    const int tid = threadIdx.x;
    const int ty = tid >> 4;
    const int tx = tid & 15;

    float acc[4][4];
#pragma unroll
    for (int i = 0; i < 4; i++)
#pragma unroll
        for (int j = 0; j < 4; j++) acc[i][j] = 0.f;

    for (int k0 = 0; k0 < DD; k0 += GBK) {
        {
            int r = tid >> 2;
            int v = tid & 3;
            float4 x4 = *(const float4*)(X + (size_t)(bm + r) * DD + k0 + v * 4);
            Xs[v * 4 + 0][r] = x4.x;
            Xs[v * 4 + 1][r] = x4.y;
            Xs[v * 4 + 2][r] = x4.z;
            Xs[v * 4 + 3][r] = x4.w;
            int wr = tid >> 4;
            int wc = tid & 15;
            *(float4*)(&Ws[wr][wc * 4]) =
                *(const float4*)(W + (size_t)(k0 + wr) * DD + bn + wc * 4);
        }
        __syncthreads();

#pragma unroll
        for (int k = 0; k < GBK; k++) {
            float4 a4 = *(const float4*)(&Xs[k][ty * 4]);
            float4 b4 = *(const float4*)(&Ws[k][tx * 4]);
            float a[4] = {a4.x, a4.y, a4.z, a4.w};
            float b[4] = {b4.x, b4.y, b4.z, b4.w};
#pragma unroll
            for (int i = 0; i < 4; i++)
#pragma unroll
                for (int j = 0; j < 4; j++)
                    acc[i][j] += a[i] * b[j];
        }
        __syncthreads();
    }

    const float4 bv = *(const float4*)(bias + bn + tx * 4);
#pragma unroll
    for (int i = 0; i < 4; i++) {
        int row = bm + ty * 4 + i;
        float4 o;
        o.x = acc[i][0] + bv.x;
        o.y = acc[i][1] + bv.y;
        o.z = acc[i][2] + bv.z;
        o.w = acc[i][3] + bv.w;
        *(float4*)(Y + (size_t)row * DD + bn + tx * 4) = o;
    }
}

// ---------------- tf32 mma flash attention ----------------
// Block: 128 q-rows, 4 warps, each warp 32 rows (2 m16 tiles). KV tile 64.
#define FTQ 128
#define FTK 64
#define QSTR 68   // bank pattern (4*rg + rt): conflict-free for A-frag loads
#define KSTR 68   // (4*jg + jt): conflict-free for K B-frag loads
#define VSTR 72   // (8*kt + pg): conflict-free for V B-frag loads

#define FLASH_SMEM_FLOATS (FTQ * QSTR + FTK * KSTR + FTK * VSTR)
#define FLASH_SMEM_BYTES  (FLASH_SMEM_FLOATS * 4)

__device__ __forceinline__ uint32_t f2tf(float f) {
    uint32_t u;
    asm("cvt.rna.tf32.f32 %0, %1;" : "=r"(u) : "f"(f));
    return u;
}
__device__ __forceinline__ float ex2(float x) {
    float y;
    asm("ex2.approx.ftz.f32 %0, %1;" : "=f"(y) : "f"(x));
    return y;
}
__device__ __forceinline__ void mma8(float* c, const uint32_t* a, uint32_t b0, uint32_t b1) {
    asm volatile(
        "mma.sync.aligned.m16n8k8.row.col.f32.tf32.tf32.f32 "
        "{%0,%1,%2,%3},{%4,%5,%6,%7},{%8,%9},{%0,%1,%2,%3};"
        : "+f"(c[0]), "+f"(c[1]), "+f"(c[2]), "+f"(c[3])
        : "r"(a[0]), "r"(a[1]), "r"(a[2]), "r"(a[3]), "r"(b0), "r"(b1));
}

__global__ __launch_bounds__(128) void flash_mma_kernel(float* __restrict__ out)
{
    extern __shared__ float sm[];
    float* Qs = sm;                    // [FTQ][QSTR]
    float* Ks = Qs + FTQ * QSTR;       // [FTK][KSTR]
    float* Vs = Ks + FTK * KSTR;       // [FTK][VSTR]

    const int tid  = threadIdx.x;
    const int lane = tid & 31;
    const int warp = tid >> 5;
    const int n0 = blockIdx.x * FTQ;
    const int h  = blockIdx.y;
    const int b  = blockIdx.z;

    const float* Qg = g_Q + ((size_t)b * NN + n0) * DD + h * PP;
    const float* Kg = g_K + (size_t)b * MM * DD + h * PP;
    const float* Vg = g_V + (size_t)b * MM * DD + h * PP;

    // fold 1/sqrt(P) and log2(e) into Q so softmax is pure ex2
    const float qscale = 0.125f * 1.4426950408889634f;

    // Q fill: one row per thread, 16 float4, scale + tf32-round
    {
        const float* src = Qg + (size_t)tid * DD;
        float* dst = Qs + tid * QSTR;
#pragma unroll
        for (int c = 0; c < 16; c++) {
            float4 v = *(const float4*)(src + c * 4);
            float4 o;
            o.x = __uint_as_float(f2tf(v.x * qscale));
            o.y = __uint_as_float(f2tf(v.y * qscale));
            o.z = __uint_as_float(f2tf(v.z * qscale));
            o.w = __uint_as_float(f2tf(v.w * qscale));
            *(float4*)(dst + c * 4) = o;
        }
    }

    const int rg = lane >> 2;   // group id (0..7)
    const int rt = lane & 3;    // thread-in-group (0..3)
    const int wm = warp * 32;   // warp's q-row base within block

    float O[2][8][4];
#pragma unroll
    for (int mt = 0; mt < 2; mt++)
#pragma unroll
        for (int nt = 0; nt < 8; nt++)
#pragma unroll
            for (int i = 0; i < 4; i++) O[mt][nt][i] = 0.f;

    float mrow[4] = {-1e30f, -1e30f, -1e30f, -1e30f};
    float lrow[4] = {0.f, 0.f, 0.f, 0.f};

    // P(C-layout) -> A(layout) shuffle sources
    const int psrc  = (lane & ~3) | (rt >> 1);
    const int psrc2 = psrc + 2;
    const bool odd  = (lane & 1);

    __syncthreads();

    for (int kt = 0; kt < MM; kt += FTK) {
        // K/V tile fill with tf32 rounding: thread t -> row t>>1, col-half t&1
        {
            int r = tid >> 1;
            int cs = (tid & 1) * 32;
            const float* ksrc = Kg + (size_t)(kt + r) * DD + cs;
            const float* vsrc = Vg + (size_t)(kt + r) * DD + cs;
            float* kdst = Ks + r * KSTR + cs;
            float* vdst = Vs + r * VSTR + cs;
#pragma unroll
            for (int c = 0; c < 8; c++) {
                float4 k4 = *(const float4*)(ksrc + c * 4);
                float4 v4 = *(const float4*)(vsrc + c * 4);
                float4 ko, vo;
                ko.x = __uint_as_float(f2tf(k4.x));
                ko.y = __uint_as_float(f2tf(k4.y));
                ko.z = __uint_as_float(f2tf(k4.z));
                ko.w = __uint_as_float(f2tf(k4.w));
                vo.x = __uint_as_float(f2tf(v4.x));
                vo.y = __uint_as_float(f2tf(v4.y));
                vo.z = __uint_as_float(f2tf(v4.z));
                vo.w = __uint_as_float(f2tf(v4.w));
                *(float4*)(kdst + c * 4) = ko;
                *(float4*)(vdst + c * 4) = vo;
            }
        }
        __syncthreads();

        // ---- S = Q K^T (exp2 domain) ----
        float S[2][8][4];
#pragma unroll
        for (int mt = 0; mt < 2; mt++)
#pragma unroll
            for (int nt = 0; nt < 8; nt++)
#pragma unroll
                for (int i = 0; i < 4; i++) S[mt][nt][i] = 0.f;

#pragma unroll
        for (int kk = 0; kk < 8; kk++) {
            uint32_t A[2][4];
#pragma unroll
            for (int mt = 0; mt < 2; mt++) {
                const float* qb = Qs + (wm + mt * 16 + rg) * QSTR + kk * 8 + rt;
                A[mt][0] = __float_as_uint(qb[0]);
                A[mt][1] = __float_as_uint(qb[8 * QSTR]);
                A[mt][2] = __float_as_uint(qb[4]);
                A[mt][3] = __float_as_uint(qb[8 * QSTR + 4]);
            }
#pragma unroll
            for (int nt = 0; nt < 8; nt++) {
                const float* kb = Ks + (nt * 8 + rg) * KSTR + kk * 8 + rt;
                uint32_t b0 = __float_as_uint(kb[0]);
                uint32_t b1 = __float_as_uint(kb[4]);
                mma8(S[0][nt], A[0], b0, b1);
                mma8(S[1][nt], A[1], b0, b1);
            }
        }

        // ---- online softmax (base-2) ----
#pragma unroll
        for (int mt = 0; mt < 2; mt++) {
#pragma unroll
            for (int half = 0; half < 2; half++) {
                const int gi = mt * 2 + half;
                float mx = -1e30f;
#pragma unroll
                for (int nt = 0; nt < 8; nt++)
                    mx = fmaxf(mx, fmaxf(S[mt][nt][half * 2], S[mt][nt][half * 2 + 1]));
                mx = fmaxf(mx, __shfl_xor_sync(0xffffffffu, mx, 1));
                mx = fmaxf(mx, __shfl_xor_sync(0xffffffffu, mx, 2));
                const float mnew = fmaxf(mrow[gi], mx);
                const float corr = ex2(mrow[gi] - mnew);
                mrow[gi] = mnew;
                lrow[gi] *= corr;
                float lsum = 0.f;
#pragma unroll
                for (int nt = 0; nt < 8; nt++) {
                    O[mt][nt][half * 2]     *= corr;
                    O[mt][nt][half * 2 + 1] *= corr;
                    float p0 = ex2(S[mt][nt][half * 2]     - mnew);
                    float p1 = ex2(S[mt][nt][half * 2 + 1] - mnew);
                    lsum += p0 + p1;
                    S[mt][nt][half * 2]     = __uint_as_float(f2tf(p0));
                    S[mt][nt][half * 2 + 1] = __uint_as_float(f2tf(p1));
                }
                lrow[gi] += lsum;
            }
        }

        // ---- O += P V ----
#pragma unroll
        for (int kk2 = 0; kk2 < 8; kk2++) {
            uint32_t A[2][4];
#pragma unroll
            for (int mt = 0; mt < 2; mt++) {
                uint32_t p0 = __float_as_uint(S[mt][kk2][0]);
                uint32_t p1 = __float_as_uint(S[mt][kk2][1]);
                uint32_t p2 = __float_as_uint(S[mt][kk2][2]);
                uint32_t p3 = __float_as_uint(S[mt][kk2][3]);
                uint32_t u0 = __shfl_sync(0xffffffffu, p0, psrc);
                uint32_t u1 = __shfl_sync(0xffffffffu, p1, psrc);
                A[mt][0] = odd ? u1 : u0;
                uint32_t u2 = __shfl_sync(0xffffffffu, p2, psrc);
                uint32_t u3 = __shfl_sync(0xffffffffu, p3, psrc);
                A[mt][1] = odd ? u3 : u2;
                uint32_t v0 = __shfl_sync(0xffffffffu, p0, psrc2);
                uint32_t v1 = __shfl_sync(0xffffffffu, p1, psrc2);
                A[mt][2] = odd ? v1 : v0;
                uint32_t v2 = __shfl_sync(0xffffffffu, p2, psrc2);
                uint32_t v3 = __shfl_sync(0xffffffffu, p3, psrc2);
                A[mt][3] = odd ? v3 : v2;
            }
#pragma unroll
            for (int nt = 0; nt < 8; nt++) {
                const float* vb = Vs + (kk2 * 8 + rt) * VSTR + nt * 8 + rg;
                uint32_t b0 = __float_as_uint(vb[0]);
                uint32_t b1 = __float_as_uint(vb[4 * VSTR]);
                mma8(O[0][nt], A[0], b0, b1);
                mma8(O[1][nt], A[1], b0, b1);
            }
        }
        __syncthreads();
    }

    // ---- epilogue: row-sum reduce l over quad, scale, store ----
#pragma unroll
    for (int gi = 0; gi < 4; gi++) {
        float l = lrow[gi];
        l += __shfl_xor_sync(0xffffffffu, l, 1);
        l += __shfl_xor_sync(0xffffffffu, l, 2);
        lrow[gi] = 1.f / l;
    }
#pragma unroll
    for (int mt = 0; mt < 2; mt++) {
#pragma unroll
        for (int half = 0; half < 2; half++) {
            const int row = n0 + wm + mt * 16 + half * 8 + rg;
            const float inv = lrow[mt * 2 + half];
            float* ob = out + ((size_t)b * NN + row) * DD + h * PP;
#pragma unroll
            for (int nt = 0; nt < 8; nt++) {
                float2 o;
                o.x = O[mt][nt][half * 2]     * inv;
                o.y = O[mt][nt][half * 2 + 1] * inv;
                *(float2*)(ob + nt * 8 + 2 * rt) = o;
            }
        }
    }
}

// ---------------- launch ----------------
extern "C" void kernel_launch(void* const* d_in, const int* in_sizes, int n_in,
                              void* d_out, int out_size)
{
    const float* queries = (const float*)d_in[0];
    const float* keys    = (const float*)d_in[1];
    const float* values  = (const float*)d_in[2];
    const float* Wq      = (const float*)d_in[3];
    const float* bq      = (const float*)d_in[4];
    const float* Wk      = (const float*)d_in[5];
    const float* bk      = (const float*)d_in[6];
    const float* Wv      = (const float*)d_in[7];
    const float* bv      = (const float*)d_in[8];
    float* out = (float*)d_out;

    float *pQ, *pK, *pV;
    cudaGetSymbolAddress((void**)&pQ, g_Q);
    cudaGetSymbolAddress((void**)&pK, g_K);
    cudaGetSymbolAddress((void**)&pV, g_V);

    dim3 ggrid(DD / GBN, (BB * NN) / GBM);
    gemm_bias_kernel<<<ggrid, 256>>>(queries, Wq, bq, pQ);
    gemm_bias_kernel<<<ggrid, 256>>>(keys,    Wk, bk, pK);
    gemm_bias_kernel<<<ggrid, 256>>>(values,  Wv, bv, pV);

    cudaFuncSetAttribute(flash_mma_kernel, cudaFuncAttributeMaxDynamicSharedMemorySize,
                         FLASH_SMEM_BYTES);
    dim3 fgrid(NN / FTQ, HH, BB);
    flash_mma_kernel<<<fgrid, 128, FLASH_SMEM_BYTES>>>(out);
}